// round 1
// baseline (speedup 1.0000x reference)
#include <cuda_runtime.h>

// Problem constants (from reference: B=32, T=512, F=513, S=3)
#define BB   32
#define NPB  262656   // T*F = 512*513
#define SS   3

// Scratch: per-batch 3x3 cost matrix sums. __device__ global (no allocs allowed).
__device__ float g_C[BB * 9];

__global__ void pil_zero_kernel() {
    int i = blockIdx.x * blockDim.x + threadIdx.x;
    if (i < BB * 9) g_C[i] = 0.0f;
}

// Accumulate sum_n |est[b,n,i] - tgt[b,n,j]| into g_C[b*9 + i*3 + j].
// grid: (BLOCKS_PER_B, BB), block: 256
__global__ void __launch_bounds__(256) pil_accum_kernel(
    const float* __restrict__ est, const float* __restrict__ tgt)
{
    const int b = blockIdx.y;
    const float* __restrict__ e = est + (size_t)b * NPB * SS;
    const float* __restrict__ t = tgt + (size_t)b * NPB * SS;

    float acc[9];
#pragma unroll
    for (int k = 0; k < 9; k++) acc[k] = 0.0f;

    const int stride = gridDim.x * blockDim.x;
    int n = blockIdx.x * blockDim.x + threadIdx.x;

    // Main loop, unrolled by 4 for memory-level parallelism.
    for (; n + 3 * stride < NPB; n += 4 * stride) {
#pragma unroll
        for (int u = 0; u < 4; u++) {
            const int m = n + u * stride;
            const float e0 = e[3 * m + 0], e1 = e[3 * m + 1], e2 = e[3 * m + 2];
            const float t0 = t[3 * m + 0], t1 = t[3 * m + 1], t2 = t[3 * m + 2];
            acc[0] += fabsf(e0 - t0); acc[1] += fabsf(e0 - t1); acc[2] += fabsf(e0 - t2);
            acc[3] += fabsf(e1 - t0); acc[4] += fabsf(e1 - t1); acc[5] += fabsf(e1 - t2);
            acc[6] += fabsf(e2 - t0); acc[7] += fabsf(e2 - t1); acc[8] += fabsf(e2 - t2);
        }
    }
    for (; n < NPB; n += stride) {
        const float e0 = e[3 * n + 0], e1 = e[3 * n + 1], e2 = e[3 * n + 2];
        const float t0 = t[3 * n + 0], t1 = t[3 * n + 1], t2 = t[3 * n + 2];
        acc[0] += fabsf(e0 - t0); acc[1] += fabsf(e0 - t1); acc[2] += fabsf(e0 - t2);
        acc[3] += fabsf(e1 - t0); acc[4] += fabsf(e1 - t1); acc[5] += fabsf(e1 - t2);
        acc[6] += fabsf(e2 - t0); acc[7] += fabsf(e2 - t1); acc[8] += fabsf(e2 - t2);
    }

    // Warp reduction (9 values per thread).
#pragma unroll
    for (int off = 16; off > 0; off >>= 1) {
#pragma unroll
        for (int k = 0; k < 9; k++)
            acc[k] += __shfl_down_sync(0xFFFFFFFFu, acc[k], off);
    }

    // Block reduction across 8 warps via shared memory.
    __shared__ float s_part[8][9];
    const int lane = threadIdx.x & 31;
    const int warp = threadIdx.x >> 5;
    if (lane == 0) {
#pragma unroll
        for (int k = 0; k < 9; k++) s_part[warp][k] = acc[k];
    }
    __syncthreads();

    if (threadIdx.x < 9) {
        float s = 0.0f;
#pragma unroll
        for (int w = 0; w < 8; w++) s += s_part[w][threadIdx.x];
        atomicAdd(&g_C[b * 9 + threadIdx.x], s);
    }
}

// Final: per-batch min over the 6 permutations of mean_j C[p[j], j], then mean over b.
__global__ void pil_final_kernel(float* __restrict__ out) {
    const int b = threadIdx.x;   // 32 threads, one per batch
    float c[9];
#pragma unroll
    for (int k = 0; k < 9; k++) c[k] = g_C[b * 9 + k] * (1.0f / (float)NPB);

    // C[i][j] = c[i*3 + j]; loss_p = (C[p0][0] + C[p1][1] + C[p2][2]) / 3
    float best = c[0] + c[4] + c[8];                      // (0,1,2)
    best = fminf(best, c[0] + c[7] + c[5]);               // (0,2,1)
    best = fminf(best, c[3] + c[1] + c[8]);               // (1,0,2)
    best = fminf(best, c[3] + c[7] + c[2]);               // (1,2,0)  -> C[1][0],C[2][1],C[0][2]
    best = fminf(best, c[6] + c[1] + c[5]);               // (2,0,1)  -> C[2][0],C[0][1],C[1][2]
    best = fminf(best, c[6] + c[4] + c[2]);               // (2,1,0)
    best *= (1.0f / 3.0f);

    // Mean over 32 batches via warp reduction.
#pragma unroll
    for (int off = 16; off > 0; off >>= 1)
        best += __shfl_down_sync(0xFFFFFFFFu, best, off);

    if (b == 0) out[0] = best * (1.0f / (float)BB);
}

extern "C" void kernel_launch(void* const* d_in, const int* in_sizes, int n_in,
                              void* d_out, int out_size) {
    const float* est = (const float*)d_in[0];
    const float* tgt = (const float*)d_in[1];
    float* out = (float*)d_out;

    pil_zero_kernel<<<1, BB * 9>>>();

    dim3 grid(64, BB);
    pil_accum_kernel<<<grid, 256>>>(est, tgt);

    pil_final_kernel<<<1, 32>>>(out);
}

// round 2
// speedup vs baseline: 1.0284x; 1.0284x over previous
#include <cuda_runtime.h>

// Problem constants (from reference: B=32, T=512, F=513, S=3)
#define BB    32
#define NPB   262656          // T*F = 512*513
#define NCHUNK (NPB / 4)      // 65664 chunks of 4 triples (12 floats) per batch
#define BLKX  32              // blocks per batch
#define NTHR  256

typedef unsigned long long u64;

// Per-block partial sums: [batch][block_x][9]. Written by pure stores (no init needed).
__device__ float g_part[BB * BLKX * 9];

__device__ __forceinline__ u64 pack2(float lo, float hi) {
    u64 r;
    asm("mov.b64 %0, {%1, %2};" : "=l"(r) : "f"(lo), "f"(hi));
    return r;
}
__device__ __forceinline__ void unpack2(float& lo, float& hi, u64 a) {
    asm("mov.b64 {%0, %1}, %2;" : "=f"(lo), "=f"(hi) : "l"(a));
}
__device__ __forceinline__ u64 sub2(u64 a, u64 b) {
    u64 r;
    asm("sub.rn.f32x2 %0, %1, %2;" : "=l"(r) : "l"(a), "l"(b));
    return r;
}
__device__ __forceinline__ u64 add2(u64 a, u64 b) {
    u64 r;
    asm("add.rn.f32x2 %0, %1, %2;" : "=l"(r) : "l"(a), "l"(b));
    return r;
}
__device__ __forceinline__ u64 abs2(u64 a) {
    return a & 0x7FFFFFFF7FFFFFFFULL;   // packed fabsf: clear both sign bits
}

// Accumulation kernel. grid (BLKX, BB), block NTHR.
// Each chunk = 12 consecutive floats = 4 triples, loaded as 3x float4 per array.
__global__ void __launch_bounds__(NTHR) pil_accum_kernel(
    const float4* __restrict__ est, const float4* __restrict__ tgt)
{
    const int b = blockIdx.y;
    const float4* __restrict__ e = est + (size_t)b * (NPB * 3 / 4);
    const float4* __restrict__ t = tgt + (size_t)b * (NPB * 3 / 4);

    u64 acc[9];
#pragma unroll
    for (int k = 0; k < 9; k++) acc[k] = 0ULL;

    const int stride = BLKX * NTHR;   // 8192 threads per batch
    for (int k = blockIdx.x * NTHR + threadIdx.x; k < NCHUNK; k += stride) {
        const float4 e0 = e[3 * k + 0], e1 = e[3 * k + 1], e2 = e[3 * k + 2];
        const float4 t0 = t[3 * k + 0], t1 = t[3 * k + 1], t2 = t[3 * k + 2];

        // Pair A = (n0, n1):  n0=(e0.x,e0.y,e0.z)  n1=(e0.w,e1.x,e1.y)
        const u64 EA0 = pack2(e0.x, e0.w), EA1 = pack2(e0.y, e1.x), EA2 = pack2(e0.z, e1.y);
        const u64 TA0 = pack2(t0.x, t0.w), TA1 = pack2(t0.y, t1.x), TA2 = pack2(t0.z, t1.y);
        // Pair B = (n2, n3):  n2=(e1.z,e1.w,e2.x)  n3=(e2.y,e2.z,e2.w)
        const u64 EB0 = pack2(e1.z, e2.y), EB1 = pack2(e1.w, e2.z), EB2 = pack2(e2.x, e2.w);
        const u64 TB0 = pack2(t1.z, t2.y), TB1 = pack2(t1.w, t2.z), TB2 = pack2(t2.x, t2.w);

        acc[0] = add2(acc[0], abs2(sub2(EA0, TA0)));
        acc[1] = add2(acc[1], abs2(sub2(EA0, TA1)));
        acc[2] = add2(acc[2], abs2(sub2(EA0, TA2)));
        acc[3] = add2(acc[3], abs2(sub2(EA1, TA0)));
        acc[4] = add2(acc[4], abs2(sub2(EA1, TA1)));
        acc[5] = add2(acc[5], abs2(sub2(EA1, TA2)));
        acc[6] = add2(acc[6], abs2(sub2(EA2, TA0)));
        acc[7] = add2(acc[7], abs2(sub2(EA2, TA1)));
        acc[8] = add2(acc[8], abs2(sub2(EA2, TA2)));

        acc[0] = add2(acc[0], abs2(sub2(EB0, TB0)));
        acc[1] = add2(acc[1], abs2(sub2(EB0, TB1)));
        acc[2] = add2(acc[2], abs2(sub2(EB0, TB2)));
        acc[3] = add2(acc[3], abs2(sub2(EB1, TB0)));
        acc[4] = add2(acc[4], abs2(sub2(EB1, TB1)));
        acc[5] = add2(acc[5], abs2(sub2(EB1, TB2)));
        acc[6] = add2(acc[6], abs2(sub2(EB2, TB0)));
        acc[7] = add2(acc[7], abs2(sub2(EB2, TB1)));
        acc[8] = add2(acc[8], abs2(sub2(EB2, TB2)));
    }

    // Collapse the packed halves to scalar partials.
    float a[9];
#pragma unroll
    for (int k = 0; k < 9; k++) {
        float lo, hi;
        unpack2(lo, hi, acc[k]);
        a[k] = lo + hi;
    }

    // Warp reduction.
#pragma unroll
    for (int off = 16; off > 0; off >>= 1) {
#pragma unroll
        for (int k = 0; k < 9; k++)
            a[k] += __shfl_down_sync(0xFFFFFFFFu, a[k], off);
    }

    // Block reduction across 8 warps.
    __shared__ float s_part[NTHR / 32][9];
    const int lane = threadIdx.x & 31;
    const int warp = threadIdx.x >> 5;
    if (lane == 0) {
#pragma unroll
        for (int k = 0; k < 9; k++) s_part[warp][k] = a[k];
    }
    __syncthreads();

    if (threadIdx.x < 9) {
        float s = 0.0f;
#pragma unroll
        for (int w = 0; w < NTHR / 32; w++) s += s_part[w][threadIdx.x];
        g_part[(b * BLKX + blockIdx.x) * 9 + threadIdx.x] = s;  // pure store, no atomics
    }
}

// Final: reduce block partials, per-batch min over 6 permutations, mean over batches.
// One block, 288 threads.
__global__ void pil_final_kernel(float* __restrict__ out) {
    __shared__ float sC[BB * 9];
    const int tid = threadIdx.x;

    if (tid < BB * 9) {
        const int b = tid / 9, k = tid % 9;
        float s = 0.0f;
#pragma unroll
        for (int x = 0; x < BLKX; x++) s += g_part[(b * BLKX + x) * 9 + k];
        sC[tid] = s * (1.0f / (float)NPB);
    }
    __syncthreads();

    if (tid < 32) {
        const float* c = &sC[tid * 9];
        // C[i][j] = c[i*3+j]; loss_p = (C[p0][0] + C[p1][1] + C[p2][2]) / 3
        float best = c[0] + c[4] + c[8];
        best = fminf(best, c[0] + c[7] + c[5]);
        best = fminf(best, c[3] + c[1] + c[8]);
        best = fminf(best, c[3] + c[7] + c[2]);
        best = fminf(best, c[6] + c[1] + c[5]);
        best = fminf(best, c[6] + c[4] + c[2]);
        best *= (1.0f / 3.0f);

#pragma unroll
        for (int off = 16; off > 0; off >>= 1)
            best += __shfl_down_sync(0xFFFFFFFFu, best, off);

        if (tid == 0) out[0] = best * (1.0f / (float)BB);
    }
}

extern "C" void kernel_launch(void* const* d_in, const int* in_sizes, int n_in,
                              void* d_out, int out_size) {
    const float4* est = (const float4*)d_in[0];
    const float4* tgt = (const float4*)d_in[1];
    float* out = (float*)d_out;

    dim3 grid(BLKX, BB);
    pil_accum_kernel<<<grid, NTHR>>>(est, tgt);
    pil_final_kernel<<<1, BB * 9>>>(out);
}

// round 3
// speedup vs baseline: 1.0548x; 1.0257x over previous
#include <cuda_runtime.h>

// Problem constants (from reference: B=32, T=512, F=513, S=3)
#define BB     32
#define NPB    262656          // T*F = 512*513
#define NCHUNK (NPB / 4)       // 65664 chunks of 4 triples (12 floats) per batch
#define BLKX   16              // blocks per batch -> 512 total CTAs (single wave @ occ 4)
#define NTHR   256
#define NBLK   (BB * BLKX)     // 512

typedef unsigned long long u64;

// Per-block partial sums: [batch][block_x][9]. Written by pure stores.
__device__ float g_part[NBLK * 9];
// Completion counter for the last-block-done pattern. Starts 0 (static init);
// the finishing block resets it to 0, so every graph replay is identical.
__device__ unsigned int g_cnt;

__device__ __forceinline__ u64 pack2(float lo, float hi) {
    u64 r;
    asm("mov.b64 %0, {%1, %2};" : "=l"(r) : "f"(lo), "f"(hi));
    return r;
}
__device__ __forceinline__ void unpack2(float& lo, float& hi, u64 a) {
    asm("mov.b64 {%0, %1}, %2;" : "=f"(lo), "=f"(hi) : "l"(a));
}
__device__ __forceinline__ u64 sub2(u64 a, u64 b) {
    u64 r;
    asm("sub.rn.f32x2 %0, %1, %2;" : "=l"(r) : "l"(a), "l"(b));
    return r;
}
__device__ __forceinline__ u64 add2(u64 a, u64 b) {
    u64 r;
    asm("add.rn.f32x2 %0, %1, %2;" : "=l"(r) : "l"(a), "l"(b));
    return r;
}
__device__ __forceinline__ u64 abs2(u64 a) {
    return a & 0x7FFFFFFF7FFFFFFFULL;   // packed fabsf: clear both sign bits
}

// Fused kernel. grid (BLKX, BB), block NTHR.
// Each chunk = 12 consecutive floats = 4 triples, loaded as 3x float4 per array.
__global__ void __launch_bounds__(NTHR, 4) pil_fused_kernel(
    const float4* __restrict__ est, const float4* __restrict__ tgt,
    float* __restrict__ out)
{
    const int b = blockIdx.y;
    const float4* __restrict__ e = est + (size_t)b * (NPB * 3 / 4);
    const float4* __restrict__ t = tgt + (size_t)b * (NPB * 3 / 4);

    u64 acc[9];
#pragma unroll
    for (int k = 0; k < 9; k++) acc[k] = 0ULL;

    const int stride = BLKX * NTHR;   // 4096 threads per batch
    for (int k = blockIdx.x * NTHR + threadIdx.x; k < NCHUNK; k += stride) {
        const float4 e0 = e[3 * k + 0], e1 = e[3 * k + 1], e2 = e[3 * k + 2];
        const float4 t0 = t[3 * k + 0], t1 = t[3 * k + 1], t2 = t[3 * k + 2];

        // Pair A = (n0, n1):  n0=(e0.x,e0.y,e0.z)  n1=(e0.w,e1.x,e1.y)
        const u64 EA0 = pack2(e0.x, e0.w), EA1 = pack2(e0.y, e1.x), EA2 = pack2(e0.z, e1.y);
        const u64 TA0 = pack2(t0.x, t0.w), TA1 = pack2(t0.y, t1.x), TA2 = pack2(t0.z, t1.y);
        // Pair B = (n2, n3):  n2=(e1.z,e1.w,e2.x)  n3=(e2.y,e2.z,e2.w)
        const u64 EB0 = pack2(e1.z, e2.y), EB1 = pack2(e1.w, e2.z), EB2 = pack2(e2.x, e2.w);
        const u64 TB0 = pack2(t1.z, t2.y), TB1 = pack2(t1.w, t2.z), TB2 = pack2(t2.x, t2.w);

        acc[0] = add2(acc[0], abs2(sub2(EA0, TA0)));
        acc[1] = add2(acc[1], abs2(sub2(EA0, TA1)));
        acc[2] = add2(acc[2], abs2(sub2(EA0, TA2)));
        acc[3] = add2(acc[3], abs2(sub2(EA1, TA0)));
        acc[4] = add2(acc[4], abs2(sub2(EA1, TA1)));
        acc[5] = add2(acc[5], abs2(sub2(EA1, TA2)));
        acc[6] = add2(acc[6], abs2(sub2(EA2, TA0)));
        acc[7] = add2(acc[7], abs2(sub2(EA2, TA1)));
        acc[8] = add2(acc[8], abs2(sub2(EA2, TA2)));

        acc[0] = add2(acc[0], abs2(sub2(EB0, TB0)));
        acc[1] = add2(acc[1], abs2(sub2(EB0, TB1)));
        acc[2] = add2(acc[2], abs2(sub2(EB0, TB2)));
        acc[3] = add2(acc[3], abs2(sub2(EB1, TB0)));
        acc[4] = add2(acc[4], abs2(sub2(EB1, TB1)));
        acc[5] = add2(acc[5], abs2(sub2(EB1, TB2)));
        acc[6] = add2(acc[6], abs2(sub2(EB2, TB0)));
        acc[7] = add2(acc[7], abs2(sub2(EB2, TB1)));
        acc[8] = add2(acc[8], abs2(sub2(EB2, TB2)));
    }

    // Collapse packed halves.
    float a[9];
#pragma unroll
    for (int k = 0; k < 9; k++) {
        float lo, hi;
        unpack2(lo, hi, acc[k]);
        a[k] = lo + hi;
    }

    // Warp reduction.
#pragma unroll
    for (int off = 16; off > 0; off >>= 1) {
#pragma unroll
        for (int k = 0; k < 9; k++)
            a[k] += __shfl_down_sync(0xFFFFFFFFu, a[k], off);
    }

    // Block reduction across 8 warps.
    __shared__ float s_part[NTHR / 32][9];
    const int lane = threadIdx.x & 31;
    const int warp = threadIdx.x >> 5;
    if (lane == 0) {
#pragma unroll
        for (int k = 0; k < 9; k++) s_part[warp][k] = a[k];
    }
    __syncthreads();

    if (threadIdx.x < 9) {
        float s = 0.0f;
#pragma unroll
        for (int w = 0; w < NTHR / 32; w++) s += s_part[w][threadIdx.x];
        g_part[(b * BLKX + blockIdx.x) * 9 + threadIdx.x] = s;
    }

    // ---- last-block-done: final reduction + permutation-min epilogue ----
    __shared__ unsigned int s_islast;
    __threadfence();                       // make g_part stores visible device-wide
    if (threadIdx.x == 0)
        s_islast = (atomicAdd(&g_cnt, 1u) == NBLK - 1);
    __syncthreads();
    if (!s_islast) return;

    __shared__ float sC[BB * 9];
    const int tid = threadIdx.x;
    // 288 entries (b,k), 256 threads: tid handles entry tid; tid<32 also entry 256+tid.
    for (int ent = tid; ent < BB * 9; ent += NTHR) {
        const int bb = ent / 9, kk = ent % 9;
        float s = 0.0f;
#pragma unroll
        for (int x = 0; x < BLKX; x++)
            s += __ldcg(&g_part[(bb * BLKX + x) * 9 + kk]);   // L2 load, skip L1
        sC[ent] = s * (1.0f / (float)NPB);
    }
    __syncthreads();

    if (tid < 32) {
        const float* c = &sC[tid * 9];
        // C[i][j] = c[i*3+j]; loss_p = (C[p0][0] + C[p1][1] + C[p2][2]) / 3
        float best = c[0] + c[4] + c[8];
        best = fminf(best, c[0] + c[7] + c[5]);
        best = fminf(best, c[3] + c[1] + c[8]);
        best = fminf(best, c[3] + c[7] + c[2]);
        best = fminf(best, c[6] + c[1] + c[5]);
        best = fminf(best, c[6] + c[4] + c[2]);
        best *= (1.0f / 3.0f);

#pragma unroll
        for (int off = 16; off > 0; off >>= 1)
            best += __shfl_down_sync(0xFFFFFFFFu, best, off);

        if (tid == 0) {
            out[0] = best * (1.0f / (float)BB);
            g_cnt = 0;                     // reset for next graph replay
        }
    }
}

extern "C" void kernel_launch(void* const* d_in, const int* in_sizes, int n_in,
                              void* d_out, int out_size) {
    const float4* est = (const float4*)d_in[0];
    const float4* tgt = (const float4*)d_in[1];
    float* out = (float*)d_out;

    dim3 grid(BLKX, BB);
    pil_fused_kernel<<<grid, NTHR>>>(est, tgt, out);
}